// round 14
// baseline (speedup 1.0000x reference)
#include <cuda_runtime.h>
#include <math.h>
#include <float.h>

#define IMG_H 128
#define IMG_W 128
#define MAXN  1024
#define NBLK  256      // 16x16 tiles of 8x8 px
#define NTHR  256      // 4 threads per pixel
#define NSUB  4
#define PXT   64
#define CHK   8        // blend chunk (independent alphas per burst)

// ---------------- device scratch (no allocations allowed) ----------------
__device__ float4 sr_q0[MAXN];   // mx, my, rad, depth
__device__ float4 sr_q1[MAXN];   // A, B, C, op
__device__ float4 sr_q2[MAXN];   // cr, cg, cb, 0
__device__ unsigned g_done = 0;
__device__ unsigned g_exit = 0;

__global__ void __launch_bounds__(NTHR)
fused_kernel(
    const float* __restrict__ means, const float* __restrict__ sh,
    const float* __restrict__ opac,  const float* __restrict__ scales,
    const float* __restrict__ rots,  const float* __restrict__ cam_pos,
    const float* __restrict__ cam_rot, const float* __restrict__ thf_p,
    const float* __restrict__ near_far, const float* __restrict__ bg,
    int n, float* __restrict__ out)
{
    const int tid = threadIdx.x;
    const int bid = blockIdx.x;

    __shared__ unsigned long long skv[MAXN];
    __shared__ float4 sA[MAXN];     // mx,my,A,B (sorted)
    __shared__ float4 sB[MAXN];     // C,op,cr,cg (sorted)
    __shared__ float  sC[MAXN];     // cb (sorted)
    __shared__ float4 comb[NSUB][PXT];
    __shared__ int    scnt;

    if (tid == NTHR - 1) scnt = 0;

    const float bg0 = bg[0], bg1 = bg[1], bg2 = bg[2];

    // ============ PHASE 1: frontend, 4 gaussians per block ============
    const int gpb = (n + NBLK - 1) / NBLK;
    const int g = bid * gpb + tid;
    if (tid < gpb && g < n) {
        const float cp0 = cam_pos[0], cp1 = cam_pos[1], cp2 = cam_pos[2];
        const float W0=cam_rot[0],W1=cam_rot[1],W2=cam_rot[2];
        const float W3=cam_rot[3],W4=cam_rot[4],W5=cam_rot[5];
        const float W6=cam_rot[6],W7=cam_rot[7],W8=cam_rot[8];

        // SH loads early: 12 x LDG.128, MLP-pipelined
        float shv[48];
        {
            const float4* sh4 = reinterpret_cast<const float4*>(sh + (size_t)g * 48);
            #pragma unroll
            for (int k = 0; k < 12; k++) {
                float4 v = sh4[k];
                shv[4*k+0] = v.x; shv[4*k+1] = v.y; shv[4*k+2] = v.z; shv[4*k+3] = v.w;
            }
        }

        float thf = thf_p[0];
        float fx = (float)IMG_W / (2.0f * thf);
        float fy = (float)IMG_H / (2.0f * thf);

        float rx = means[3*g+0] - cp0;
        float ry = means[3*g+1] - cp1;
        float rz = means[3*g+2] - cp2;

        float t0 = W0*rx + W1*ry + W2*rz;
        float t1 = W3*rx + W4*ry + W5*rz;
        float tz = W6*rx + W7*ry + W8*rz;

        float lim = 1.3f * thf;
        float invz = __fdividef(1.0f, tz);
        float txz = t0 * invz, tyz = t1 * invz;
        float txc = fminf(fmaxf(txz, -lim), lim) * tz;
        float tyc = fminf(fmaxf(tyz, -lim), lim) * tz;

        float qr = rots[4*g+0], qx = rots[4*g+1], qy = rots[4*g+2], qz = rots[4*g+3];
        float qn = rsqrtf(qr*qr + qx*qx + qy*qy + qz*qz);
        qr*=qn; qx*=qn; qy*=qn; qz*=qn;
        float R00 = 1.f - 2.f*(qy*qy + qz*qz), R01 = 2.f*(qx*qy - qr*qz), R02 = 2.f*(qx*qz + qr*qy);
        float R10 = 2.f*(qx*qy + qr*qz), R11 = 1.f - 2.f*(qx*qx + qz*qz), R12 = 2.f*(qy*qz - qr*qx);
        float R20 = 2.f*(qx*qz - qr*qy), R21 = 2.f*(qy*qz + qr*qx), R22 = 1.f - 2.f*(qx*qx + qy*qy);

        float s0 = scales[3*g+0], s1 = scales[3*g+1], s2 = scales[3*g+2];
        float M00=R00*s0, M01=R01*s1, M02=R02*s2;
        float M10=R10*s0, M11=R11*s1, M12=R12*s2;
        float M20=R20*s0, M21=R21*s1, M22=R22*s2;

        float c00 = M00*M00 + M01*M01 + M02*M02;
        float c01 = M00*M10 + M01*M11 + M02*M12;
        float c02 = M00*M20 + M01*M21 + M02*M22;
        float c11 = M10*M10 + M11*M11 + M12*M12;
        float c12 = M10*M20 + M11*M21 + M12*M22;
        float c22 = M20*M20 + M21*M21 + M22*M22;

        float J00 = fx * invz, J02 = -fx * txc * invz * invz;
        float J11 = fy * invz, J12 = -fy * tyc * invz * invz;

        float T00 = J00*W0 + J02*W6, T01 = J00*W1 + J02*W7, T02 = J00*W2 + J02*W8;
        float T10 = J11*W3 + J12*W6, T11 = J11*W4 + J12*W7, T12 = J11*W5 + J12*W8;

        float V00 = T00*c00 + T01*c01 + T02*c02;
        float V01 = T00*c01 + T01*c11 + T02*c12;
        float V02 = T00*c02 + T01*c12 + T02*c22;
        float V10 = T10*c00 + T11*c01 + T12*c02;
        float V11 = T10*c01 + T11*c11 + T12*c12;
        float V12 = T10*c02 + T11*c12 + T12*c22;

        float cov00 = V00*T00 + V01*T01 + V02*T02;
        float cov01 = V00*T10 + V01*T11 + V02*T12;
        float cov11 = V10*T10 + V11*T11 + V12*T12;

        float a = cov00 + 0.3f, c = cov11 + 0.3f, b = cov01;
        float det = a*c - b*b;
        bool valid = (tz > near_far[0]) && (tz < near_far[1]) && (det > 0.0f);

        float invDet = __fdividef(1.0f, det);
        float A =  c * invDet;
        float B = -b * invDet;
        float C =  a * invDet;

        float mx = fx * txz + ((float)IMG_W - 1.0f) * 0.5f;
        float my = fy * tyz + ((float)IMG_H - 1.0f) * 0.5f;

        float dn = rsqrtf(rx*rx + ry*ry + rz*rz);
        float dx = rx*dn, dy = ry*dn, dz = rz*dn;
        float xx = dx*dx, yy = dy*dy, zz = dz*dz;
        float xy = dx*dy, yz = dy*dz, xz = dx*dz;

        float bas[16];
        bas[0]  =  0.28209479177387814f;
        bas[1]  = -0.4886025119029199f * dy;
        bas[2]  =  0.4886025119029199f * dz;
        bas[3]  = -0.4886025119029199f * dx;
        bas[4]  =  1.0925484305920792f * xy;
        bas[5]  = -1.0925484305920792f * yz;
        bas[6]  =  0.31539156525252005f * (2.0f*zz - xx - yy);
        bas[7]  = -1.0925484305920792f * xz;
        bas[8]  =  0.5462742152960396f * (xx - yy);
        bas[9]  = -0.5900435899266435f * dy * (3.0f*xx - yy);
        bas[10] =  2.890611442640554f  * xy * dz;
        bas[11] = -0.4570457994644658f * dy * (4.0f*zz - xx - yy);
        bas[12] =  0.3731763325901154f * dz * (2.0f*zz - 3.0f*xx - 3.0f*yy);
        bas[13] = -0.4570457994644658f * dx * (4.0f*zz - xx - yy);
        bas[14] =  1.445305721320277f  * dz * (xx - yy);
        bas[15] = -0.5900435899266435f * dx * (xx - 3.0f*yy);

        float col[3];
        #pragma unroll
        for (int ch = 0; ch < 3; ch++) {
            float r = 0.0f;
            #pragma unroll
            for (int k = 0; k < 16; k++) r += bas[k] * shv[k*3 + ch];
            col[ch] = fmaxf(r + 0.5f, 0.0f);
        }

        float o = opac[g];

        float rad;
        if (!valid) {
            rad = -1.0f;
        } else {
            float thr = __logf(255.0f * o);
            if (thr <= 0.0f) {
                rad = -1.0f;
            } else {
                float disc = sqrtf(fmaxf((A - C)*(A - C) + 4.0f*B*B, 0.0f));
                float lamMin = 0.5f * ((A + C) - disc);
                if (lamMin < 1e-12f) rad = 1e9f;
                else rad = sqrtf(__fdividef(2.0f * thr, lamMin)) * 1.01f + 2.0f;
            }
        }

        sr_q0[g] = make_float4(mx, my, rad, tz);
        sr_q1[g] = make_float4(A, B, C, o);
        sr_q2[g] = make_float4(col[0], col[1], col[2], 0.0f);
        __threadfence();
    }
    __syncthreads();

    // ============ grid barrier: volatile-load poll ============
    if (tid == 0) {
        atomicAdd(&g_done, 1u);
        volatile unsigned* vd = &g_done;
        while (*vd < (unsigned)NBLK) { }
        __threadfence();
    }
    __syncthreads();

    // ============ PHASE 2: rasterize one 8x8 tile, 4 threads/pixel ============
    {
        const int tileX = bid & 15;
        const int tileY = bid >> 4;
        const int px  = tid & 63;
        const int sub = tid >> 6;
        const int lx = px & 7, ly = px >> 3;
        const int pxI = tileX * 8 + lx;
        const int pyI = tileY * 8 + ly;
        const float pxf = (float)pxI, pyf = (float)pyI;

        const float tx0 = (float)(tileX * 8);
        const float tx1 = (float)(tileX * 8 + 7);
        const float ty0 = (float)(tileY * 8);
        const float ty1 = (float)(tileY * 8 + 7);

        // ---- cull: 4 rounds, MLP-pipelined ----
        for (int gg = tid; gg < n; gg += NTHR) {
            float4 q0 = sr_q0[gg];
            float r = q0.z;
            bool pass = (r > 0.0f) &&
                        (q0.x + r >= tx0) && (q0.x - r <= tx1) &&
                        (q0.y + r >= ty0) && (q0.y - r <= ty1);
            if (pass) {
                int p = atomicAdd(&scnt, 1);
                skv[p] = ((unsigned long long)__float_as_uint(q0.w) << 32) | (unsigned)gg;
            }
        }
        __syncthreads();
        const int tot = scnt;

        // ---- local stable rank sort + fused gather ----
        for (int i = tid; i < tot; i += NTHR) {
            unsigned long long ki = skv[i];
            int gi = (int)(ki & 0xffffffffu);
            float4 q0 = sr_q0[gi];
            float4 q1 = sr_q1[gi];
            float4 q2 = sr_q2[gi];
            int rank = 0;
            for (int j = 0; j < tot; j++) {
                rank += (skv[j] < ki);
            }
            sA[rank] = make_float4(q0.x, q0.y, q1.x, q1.y);
            sB[rank] = make_float4(q1.z, q1.w, q2.x, q2.y);
            sC[rank] = q2.z;
        }
        __syncthreads();

        // ---- segmented blend, chunked: 8 independent alphas per burst ----
        const int seg = (tot + NSUB - 1) >> 2;
        const int j0 = sub * seg;
        const int j1 = min(j0 + seg, tot);

        float T = 1.0f, accR = 0.0f, accG = 0.0f, accB = 0.0f;
        for (int j = j0; j < j1; j += CHK) {
            const int m = min(CHK, j1 - j);
            float al[CHK], cr[CHK], cg[CHK], cbv[CHK];
            // burst: independent alpha computations, MUFU-pipelined
            #pragma unroll
            for (int k = 0; k < CHK; k++) {
                if (k < m) {
                    float4 q1 = sA[j + k];
                    float4 q2 = sB[j + k];
                    cbv[k] = sC[j + k];
                    float ddx = pxf - q1.x;
                    float ddy = pyf - q1.y;
                    float power = -0.5f * (q1.z*ddx*ddx + q2.x*ddy*ddy) - q1.w*ddx*ddy;
                    float alpha = fminf(q2.y * __expf(power), 0.99f);
                    bool ok = (power <= 0.0f) && (alpha >= 0.00392156862745098f);
                    al[k] = ok ? alpha : 0.0f;
                    cr[k] = q2.z;
                    cg[k] = q2.w;
                } else {
                    al[k] = 0.0f; cr[k] = 0.0f; cg[k] = 0.0f; cbv[k] = 0.0f;
                }
            }
            // short serial combine (2 FMA-chain ops per entry)
            #pragma unroll
            for (int k = 0; k < CHK; k++) {
                float w = al[k] * T;
                accR += w * cr[k];
                accG += w * cg[k];
                accB += w * cbv[k];
                T *= (1.0f - al[k]);
            }
            if (T < 1e-7f) break;   // residual < 1e-7 absolute
        }
        comb[sub][px] = make_float4(accR, accG, accB, T);
        __syncthreads();

        // ---- in-order composition; subs 0..2 each store one channel ----
        if (sub < 3) {
            float4 s0 = comb[0][px];
            float aR = s0.x, aG = s0.y, aB = s0.z, Tt = s0.w;
            #pragma unroll
            for (int s = 1; s < NSUB; s++) {
                float4 ss = comb[s][px];
                aR += Tt * ss.x;
                aG += Tt * ss.y;
                aB += Tt * ss.z;
                Tt *= ss.w;
            }
            const int pix = pyI * IMG_W + pxI;
            float v = (sub == 0) ? (aR + Tt * bg0)
                    : (sub == 1) ? (aG + Tt * bg1)
                                 : (aB + Tt * bg2);
            out[sub * IMG_H * IMG_W + pix] = v;
        }
    }

    // ============ reset counters for next graph replay ============
    if (tid == 0) {
        unsigned old = atomicAdd(&g_exit, 1u);
        if (old == (unsigned)(NBLK - 1)) {
            atomicExch(&g_done, 0u);
            atomicExch(&g_exit, 0u);
        }
    }
}

// ---------------- launch ----------------
extern "C" void kernel_launch(void* const* d_in, const int* in_sizes, int n_in,
                              void* d_out, int out_size)
{
    const float* means    = (const float*)d_in[0];
    const float* sh       = (const float*)d_in[1];
    const float* opac     = (const float*)d_in[2];
    const float* scales   = (const float*)d_in[3];
    const float* rots     = (const float*)d_in[4];
    const float* cam_pos  = (const float*)d_in[5];
    const float* cam_rot  = (const float*)d_in[6];
    const float* thf      = (const float*)d_in[7];
    const float* bg       = (const float*)d_in[8];
    const float* near_far = (const float*)d_in[9];

    int n = in_sizes[0] / 3;
    if (n > MAXN) n = MAXN;

    fused_kernel<<<NBLK, NTHR>>>(means, sh, opac, scales, rots,
                                 cam_pos, cam_rot, thf, near_far, bg,
                                 n, (float*)d_out);
}

// round 15
// speedup vs baseline: 1.1600x; 1.1600x over previous
#include <cuda_runtime.h>
#include <math.h>
#include <float.h>

#define IMG_H 128
#define IMG_W 128
#define MAXN  1024
#define NBLK  256      // 16x16 tiles of 8x8 px
#define NTHR  256      // 4 threads per pixel
#define NSUB  4
#define PXT   64

// ---------------- device scratch (no allocations allowed) ----------------
__device__ float4 sr_q0[MAXN];   // mx, my, rad, depth
__device__ float4 sr_q1[MAXN];   // A, B, C, op
__device__ float4 sr_q2[MAXN];   // cr, cg, cb, 0
__device__ unsigned g_done = 0;
__device__ unsigned g_exit = 0;

__global__ void __launch_bounds__(NTHR)
fused_kernel(
    const float* __restrict__ means, const float* __restrict__ sh,
    const float* __restrict__ opac,  const float* __restrict__ scales,
    const float* __restrict__ rots,  const float* __restrict__ cam_pos,
    const float* __restrict__ cam_rot, const float* __restrict__ thf_p,
    const float* __restrict__ near_far, const float* __restrict__ bg,
    int n, float* __restrict__ out)
{
    const int tid = threadIdx.x;
    const int bid = blockIdx.x;

    __shared__ unsigned long long skv[MAXN];   // (depth_bits<<32)|idx
    __shared__ float4 sA[MAXN];     // mx,my,A,B (sorted)
    __shared__ float4 sB[MAXN];     // C,op,cr,cg (sorted)
    __shared__ float  sC[MAXN];     // cb (sorted)
    __shared__ float4 comb[NSUB][PXT];
    __shared__ int    scnt;

    if (tid == NTHR - 1) scnt = 0;   // folded into the pre-barrier sync

    const float bg0 = bg[0], bg1 = bg[1], bg2 = bg[2];

    // ============ PHASE 1: frontend, 4 gaussians per block ============
    const int gpb = (n + NBLK - 1) / NBLK;
    const int g = bid * gpb + tid;
    if (tid < gpb && g < n) {
        const float cp0 = cam_pos[0], cp1 = cam_pos[1], cp2 = cam_pos[2];
        const float W0=cam_rot[0],W1=cam_rot[1],W2=cam_rot[2];
        const float W3=cam_rot[3],W4=cam_rot[4],W5=cam_rot[5];
        const float W6=cam_rot[6],W7=cam_rot[7],W8=cam_rot[8];

        // SH loads early: 12 x LDG.128, MLP-pipelined
        float shv[48];
        {
            const float4* sh4 = reinterpret_cast<const float4*>(sh + (size_t)g * 48);
            #pragma unroll
            for (int k = 0; k < 12; k++) {
                float4 v = sh4[k];
                shv[4*k+0] = v.x; shv[4*k+1] = v.y; shv[4*k+2] = v.z; shv[4*k+3] = v.w;
            }
        }

        float thf = thf_p[0];
        float fx = (float)IMG_W / (2.0f * thf);
        float fy = (float)IMG_H / (2.0f * thf);

        float rx = means[3*g+0] - cp0;
        float ry = means[3*g+1] - cp1;
        float rz = means[3*g+2] - cp2;

        float t0 = W0*rx + W1*ry + W2*rz;
        float t1 = W3*rx + W4*ry + W5*rz;
        float tz = W6*rx + W7*ry + W8*rz;

        float lim = 1.3f * thf;
        float invz = __fdividef(1.0f, tz);
        float txz = t0 * invz, tyz = t1 * invz;
        float txc = fminf(fmaxf(txz, -lim), lim) * tz;
        float tyc = fminf(fmaxf(tyz, -lim), lim) * tz;

        float qr = rots[4*g+0], qx = rots[4*g+1], qy = rots[4*g+2], qz = rots[4*g+3];
        float qn = rsqrtf(qr*qr + qx*qx + qy*qy + qz*qz);
        qr*=qn; qx*=qn; qy*=qn; qz*=qn;
        float R00 = 1.f - 2.f*(qy*qy + qz*qz), R01 = 2.f*(qx*qy - qr*qz), R02 = 2.f*(qx*qz + qr*qy);
        float R10 = 2.f*(qx*qy + qr*qz), R11 = 1.f - 2.f*(qx*qx + qz*qz), R12 = 2.f*(qy*qz - qr*qx);
        float R20 = 2.f*(qx*qz - qr*qy), R21 = 2.f*(qy*qz + qr*qx), R22 = 1.f - 2.f*(qx*qx + qy*qy);

        float s0 = scales[3*g+0], s1 = scales[3*g+1], s2 = scales[3*g+2];
        float M00=R00*s0, M01=R01*s1, M02=R02*s2;
        float M10=R10*s0, M11=R11*s1, M12=R12*s2;
        float M20=R20*s0, M21=R21*s1, M22=R22*s2;

        float c00 = M00*M00 + M01*M01 + M02*M02;
        float c01 = M00*M10 + M01*M11 + M02*M12;
        float c02 = M00*M20 + M01*M21 + M02*M22;
        float c11 = M10*M10 + M11*M11 + M12*M12;
        float c12 = M10*M20 + M11*M21 + M12*M22;
        float c22 = M20*M20 + M21*M21 + M22*M22;

        float J00 = fx * invz, J02 = -fx * txc * invz * invz;
        float J11 = fy * invz, J12 = -fy * tyc * invz * invz;

        float T00 = J00*W0 + J02*W6, T01 = J00*W1 + J02*W7, T02 = J00*W2 + J02*W8;
        float T10 = J11*W3 + J12*W6, T11 = J11*W4 + J12*W7, T12 = J11*W5 + J12*W8;

        float V00 = T00*c00 + T01*c01 + T02*c02;
        float V01 = T00*c01 + T01*c11 + T02*c12;
        float V02 = T00*c02 + T01*c12 + T02*c22;
        float V10 = T10*c00 + T11*c01 + T12*c02;
        float V11 = T10*c01 + T11*c11 + T12*c12;
        float V12 = T10*c02 + T11*c12 + T12*c22;

        float cov00 = V00*T00 + V01*T01 + V02*T02;
        float cov01 = V00*T10 + V01*T11 + V02*T12;
        float cov11 = V10*T10 + V11*T11 + V12*T12;

        float a = cov00 + 0.3f, c = cov11 + 0.3f, b = cov01;
        float det = a*c - b*b;
        bool valid = (tz > near_far[0]) && (tz < near_far[1]) && (det > 0.0f);

        float invDet = __fdividef(1.0f, det);
        float A =  c * invDet;
        float B = -b * invDet;
        float C =  a * invDet;

        float mx = fx * txz + ((float)IMG_W - 1.0f) * 0.5f;
        float my = fy * tyz + ((float)IMG_H - 1.0f) * 0.5f;

        float dn = rsqrtf(rx*rx + ry*ry + rz*rz);
        float dx = rx*dn, dy = ry*dn, dz = rz*dn;
        float xx = dx*dx, yy = dy*dy, zz = dz*dz;
        float xy = dx*dy, yz = dy*dz, xz = dx*dz;

        float bas[16];
        bas[0]  =  0.28209479177387814f;
        bas[1]  = -0.4886025119029199f * dy;
        bas[2]  =  0.4886025119029199f * dz;
        bas[3]  = -0.4886025119029199f * dx;
        bas[4]  =  1.0925484305920792f * xy;
        bas[5]  = -1.0925484305920792f * yz;
        bas[6]  =  0.31539156525252005f * (2.0f*zz - xx - yy);
        bas[7]  = -1.0925484305920792f * xz;
        bas[8]  =  0.5462742152960396f * (xx - yy);
        bas[9]  = -0.5900435899266435f * dy * (3.0f*xx - yy);
        bas[10] =  2.890611442640554f  * xy * dz;
        bas[11] = -0.4570457994644658f * dy * (4.0f*zz - xx - yy);
        bas[12] =  0.3731763325901154f * dz * (2.0f*zz - 3.0f*xx - 3.0f*yy);
        bas[13] = -0.4570457994644658f * dx * (4.0f*zz - xx - yy);
        bas[14] =  1.445305721320277f  * dz * (xx - yy);
        bas[15] = -0.5900435899266435f * dx * (xx - 3.0f*yy);

        float col[3];
        #pragma unroll
        for (int ch = 0; ch < 3; ch++) {
            float r = 0.0f;
            #pragma unroll
            for (int k = 0; k < 16; k++) r += bas[k] * shv[k*3 + ch];
            col[ch] = fmaxf(r + 0.5f, 0.0f);
        }

        float o = opac[g];

        float rad;
        if (!valid) {
            rad = -1.0f;
        } else {
            float thr = __logf(255.0f * o);
            if (thr <= 0.0f) {
                rad = -1.0f;
            } else {
                float disc = sqrtf(fmaxf((A - C)*(A - C) + 4.0f*B*B, 0.0f));
                float lamMin = 0.5f * ((A + C) - disc);
                if (lamMin < 1e-12f) rad = 1e9f;
                else rad = sqrtf(__fdividef(2.0f * thr, lamMin)) * 1.01f + 2.0f;
            }
        }

        sr_q0[g] = make_float4(mx, my, rad, tz);
        sr_q1[g] = make_float4(A, B, C, o);
        sr_q2[g] = make_float4(col[0], col[1], col[2], 0.0f);
        __threadfence();
    }
    __syncthreads();

    // ============ grid barrier: volatile-load poll ============
    if (tid == 0) {
        atomicAdd(&g_done, 1u);
        volatile unsigned* vd = &g_done;
        while (*vd < (unsigned)NBLK) { }
        __threadfence();
    }
    __syncthreads();

    // ============ PHASE 2: rasterize one 8x8 tile, 4 threads/pixel ============
    {
        const int tileX = bid & 15;
        const int tileY = bid >> 4;
        const int px  = tid & 63;
        const int sub = tid >> 6;
        const int lx = px & 7, ly = px >> 3;
        const int pxI = tileX * 8 + lx;
        const int pyI = tileY * 8 + ly;
        const float pxf = (float)pxI, pyf = (float)pyI;

        const float tx0 = (float)(tileX * 8);
        const float tx1 = (float)(tileX * 8 + 7);
        const float ty0 = (float)(tileY * 8);
        const float ty1 = (float)(tileY * 8 + 7);

        // ---- cull: 4 rounds, MLP-pipelined ----
        for (int gg = tid; gg < n; gg += NTHR) {
            float4 q0 = sr_q0[gg];
            float r = q0.z;
            bool pass = (r > 0.0f) &&
                        (q0.x + r >= tx0) && (q0.x - r <= tx1) &&
                        (q0.y + r >= ty0) && (q0.y - r <= ty1);
            if (pass) {
                int p = atomicAdd(&scnt, 1);
                skv[p] = ((unsigned long long)__float_as_uint(q0.w) << 32) | (unsigned)gg;
            }
        }
        __syncthreads();
        const int tot = scnt;

        // ---- local stable rank sort + fused gather ----
        for (int i = tid; i < tot; i += NTHR) {
            unsigned long long ki = skv[i];
            int gi = (int)(ki & 0xffffffffu);
            float4 q0 = sr_q0[gi];
            float4 q1 = sr_q1[gi];
            float4 q2 = sr_q2[gi];
            int rank = 0;
            for (int j = 0; j < tot; j++) {
                rank += (skv[j] < ki);
            }
            sA[rank] = make_float4(q0.x, q0.y, q1.x, q1.y);
            sB[rank] = make_float4(q1.z, q1.w, q2.x, q2.y);
            sC[rank] = q2.z;
        }
        __syncthreads();

        // ---- segmented blend: each sub blends a contiguous quarter ----
        const int seg = (tot + NSUB - 1) >> 2;
        const int j0 = sub * seg;
        const int j1 = min(j0 + seg, tot);

        float T = 1.0f, accR = 0.0f, accG = 0.0f, accB = 0.0f;
        #pragma unroll 2
        for (int j = j0; j < j1; j++) {
            float4 q1 = sA[j];
            float4 q2 = sB[j];
            float cb = sC[j];
            float ddx = pxf - q1.x;
            float ddy = pyf - q1.y;
            float power = -0.5f * (q1.z*ddx*ddx + q2.x*ddy*ddy) - q1.w*ddx*ddy;
            float alpha = fminf(q2.y * __expf(power), 0.99f);
            bool ok = (power <= 0.0f) && (alpha >= 0.00392156862745098f);
            alpha = ok ? alpha : 0.0f;
            float w = alpha * T;
            accR += w * q2.z;
            accG += w * q2.w;
            accB += w * cb;
            T *= (1.0f - alpha);
            if (T < 1e-7f) break;
        }
        comb[sub][px] = make_float4(accR, accG, accB, T);
        __syncthreads();

        // ---- in-order composition; subs 0..2 each store one channel ----
        if (sub < 3) {
            float4 s0 = comb[0][px];
            float aR = s0.x, aG = s0.y, aB = s0.z, Tt = s0.w;
            #pragma unroll
            for (int s = 1; s < NSUB; s++) {
                float4 ss = comb[s][px];
                aR += Tt * ss.x;
                aG += Tt * ss.y;
                aB += Tt * ss.z;
                Tt *= ss.w;
            }
            const int pix = pyI * IMG_W + pxI;
            float v = (sub == 0) ? (aR + Tt * bg0)
                    : (sub == 1) ? (aG + Tt * bg1)
                                 : (aB + Tt * bg2);
            out[sub * IMG_H * IMG_W + pix] = v;
        }
    }

    // ============ reset counters for next graph replay ============
    if (tid == 0) {
        unsigned old = atomicAdd(&g_exit, 1u);
        if (old == (unsigned)(NBLK - 1)) {
            atomicExch(&g_done, 0u);
            atomicExch(&g_exit, 0u);
        }
    }
}

// ---------------- launch ----------------
extern "C" void kernel_launch(void* const* d_in, const int* in_sizes, int n_in,
                              void* d_out, int out_size)
{
    const float* means    = (const float*)d_in[0];
    const float* sh       = (const float*)d_in[1];
    const float* opac     = (const float*)d_in[2];
    const float* scales   = (const float*)d_in[3];
    const float* rots     = (const float*)d_in[4];
    const float* cam_pos  = (const float*)d_in[5];
    const float* cam_rot  = (const float*)d_in[6];
    const float* thf      = (const float*)d_in[7];
    const float* bg       = (const float*)d_in[8];
    const float* near_far = (const float*)d_in[9];

    int n = in_sizes[0] / 3;
    if (n > MAXN) n = MAXN;

    fused_kernel<<<NBLK, NTHR>>>(means, sh, opac, scales, rots,
                                 cam_pos, cam_rot, thf, near_far, bg,
                                 n, (float*)d_out);
}